// round 9
// baseline (speedup 1.0000x reference)
#include <cuda_runtime.h>
#include <cuda_bf16.h>
#include <cstdint>

// out[b,i,j] = Vx(i; t0,t2) * Vy(j; t1,t2), with
//   t = x @ (W1@W2) + (b1@W2 + b2)   (the two linears collapse)
// Kernel A: Weff[1024,3] (split arrays) + beff[3], W2 staged in smem.
// Kernel B: PERSISTENT single-wave grid (7 blocks/SM x 148 SMs), each warp
//   grid-strides over batch rows: float4 GEMV -> boxcar -> STG.128 raster
//   (row = 14 float4; lanes 0-13 store row 2p, lanes 14-27 store row 2p+1).

#define MAX_D 1024
#define MAX_H 512
#define S 56
#define KSTEEP 10.0f
#define NSM 148
#define BLK_PER_SM 7

__device__ float g_w0[MAX_D];
__device__ float g_w1[MAX_D];
__device__ float g_w2[MAX_D];
__device__ float g_beff[3];

// ---------------------------------------------------------------------------
// Kernel A: Weff = W1 @ W2 (warp per d-row, W2 staged in smem),
//           beff = b1 @ W2 + b2 (one warp in block 0).
// ---------------------------------------------------------------------------
__global__ __launch_bounds__(256) void weff_kernel(const float* __restrict__ W1,
                                                   const float* __restrict__ b1,
                                                   const float* __restrict__ W2,
                                                   const float* __restrict__ b2,
                                                   int D, int H) {
    __shared__ float s_W2[MAX_H * 3];

    const int nW2 = H * 3;
    for (int idx = threadIdx.x; idx < nW2; idx += blockDim.x)
        s_W2[idx] = W2[idx];
    __syncthreads();

    const int lane = threadIdx.x & 31;
    const int warp = (blockIdx.x * blockDim.x + threadIdx.x) >> 5;

    if (warp < D) {
        const float4* __restrict__ row4 = (const float4*)(W1 + (size_t)warp * H);
        const int nch = H >> 2;
        float a0 = 0.f, a1 = 0.f, a2 = 0.f;
        #pragma unroll 4
        for (int c = lane; c < nch; c += 32) {
            float4 w = row4[c];
            int h = c << 2;
            a0 = fmaf(w.x, s_W2[(h+0)*3+0], fmaf(w.y, s_W2[(h+1)*3+0],
                 fmaf(w.z, s_W2[(h+2)*3+0], fmaf(w.w, s_W2[(h+3)*3+0], a0))));
            a1 = fmaf(w.x, s_W2[(h+0)*3+1], fmaf(w.y, s_W2[(h+1)*3+1],
                 fmaf(w.z, s_W2[(h+2)*3+1], fmaf(w.w, s_W2[(h+3)*3+1], a1))));
            a2 = fmaf(w.x, s_W2[(h+0)*3+2], fmaf(w.y, s_W2[(h+1)*3+2],
                 fmaf(w.z, s_W2[(h+2)*3+2], fmaf(w.w, s_W2[(h+3)*3+2], a2))));
        }
        #pragma unroll
        for (int o = 16; o > 0; o >>= 1) {
            a0 += __shfl_xor_sync(0xffffffffu, a0, o);
            a1 += __shfl_xor_sync(0xffffffffu, a1, o);
            a2 += __shfl_xor_sync(0xffffffffu, a2, o);
        }
        if (lane == 0) {
            g_w0[warp] = a0;
            g_w1[warp] = a1;
            g_w2[warp] = a2;
        }
    }

    if (blockIdx.x == 0 && threadIdx.x < 32) {
        float s0 = 0.f, s1 = 0.f, s2 = 0.f;
        for (int h = lane; h < H; h += 32) {
            float bv = b1[h];
            s0 = fmaf(bv, s_W2[h * 3 + 0], s0);
            s1 = fmaf(bv, s_W2[h * 3 + 1], s1);
            s2 = fmaf(bv, s_W2[h * 3 + 2], s2);
        }
        #pragma unroll
        for (int o = 16; o > 0; o >>= 1) {
            s0 += __shfl_xor_sync(0xffffffffu, s0, o);
            s1 += __shfl_xor_sync(0xffffffffu, s1, o);
            s2 += __shfl_xor_sync(0xffffffffu, s2, o);
        }
        if (lane == 0) {
            g_beff[0] = s0 + b2[0];
            g_beff[1] = s1 + b2[1];
            g_beff[2] = s2 + b2[2];
        }
    }
}

// ---------------------------------------------------------------------------
// Kernel B: persistent, warp grid-strides over batch rows.
// ---------------------------------------------------------------------------
__device__ __forceinline__ float fsigmoid(float z) {
    return 1.0f / (1.0f + __expf(-z));
}

__global__ __launch_bounds__(256, BLK_PER_SM) void boxcar_kernel(
        const float* __restrict__ x, float* __restrict__ out, int B, int D) {
    __shared__ __align__(16) float s_w0[MAX_D];
    __shared__ __align__(16) float s_w1[MAX_D];
    __shared__ __align__(16) float s_w2[MAX_D];

    for (int e = threadIdx.x; e < D; e += blockDim.x) {
        s_w0[e] = g_w0[e];
        s_w1[e] = g_w1[e];
        s_w2[e] = g_w2[e];
    }
    __syncthreads();

    const int lane   = threadIdx.x & 31;
    const int wid    = threadIdx.x >> 5;
    const int gwarp  = blockIdx.x * (blockDim.x >> 5) + wid;
    const int nwarps = gridDim.x * (blockDim.x >> 5);
    const int nch    = D >> 2;                  // 256 for D=1024

    const float be0 = g_beff[0];
    const float be1 = g_beff[1];
    const float be2 = g_beff[2];

    // lane -> (which half-row, which float4 column)
    const int c14 = (lane < 14) ? lane : lane - 14;   // 0..13 (garbage >27 unused)

    for (int r = gwarp; r < B; r += nwarps) {
        // ---- skinny GEMV, float4: 8 LDG.128 + 24 LDS.128 per lane ----
        const float4* __restrict__ x4 = (const float4*)(x + (size_t)r * D);
        float a0 = 0.f, a1 = 0.f, a2 = 0.f;
        #pragma unroll 4
        for (int c = lane; c < nch; c += 32) {
            float4 xv = x4[c];
            int e = c << 2;
            float4 w0 = *(const float4*)&s_w0[e];
            float4 w1 = *(const float4*)&s_w1[e];
            float4 w2 = *(const float4*)&s_w2[e];
            a0 = fmaf(xv.x, w0.x, fmaf(xv.y, w0.y, fmaf(xv.z, w0.z, fmaf(xv.w, w0.w, a0))));
            a1 = fmaf(xv.x, w1.x, fmaf(xv.y, w1.y, fmaf(xv.z, w1.z, fmaf(xv.w, w1.w, a1))));
            a2 = fmaf(xv.x, w2.x, fmaf(xv.y, w2.y, fmaf(xv.z, w2.z, fmaf(xv.w, w2.w, a2))));
        }
        #pragma unroll
        for (int o = 16; o > 0; o >>= 1) {
            a0 += __shfl_xor_sync(0xffffffffu, a0, o);
            a1 += __shfl_xor_sync(0xffffffffu, a1, o);
            a2 += __shfl_xor_sync(0xffffffffu, a2, o);
        }
        const float t0 = a0 + be0;   // x center (rows i)
        const float t1 = a1 + be1;   // y center (cols j)
        const float t2 = a2 + be2;   // size

        // ---- boxcar profiles: lane covers coords lane and lane+32 ----
        const float half = 0.5f * t2;
        const float p0 = (float)lane;
        const float p1 = (float)(lane + 32);

        float vx0 = fsigmoid(KSTEEP * (p0 - t0 + half)) - fsigmoid(KSTEEP * (p0 - t0 - half));
        float vy0 = fsigmoid(KSTEEP * (p0 - t1 + half)) - fsigmoid(KSTEEP * (p0 - t1 - half));
        float vx1 = 0.f, vy1 = 0.f;
        if (lane < S - 32) {
            vx1 = fsigmoid(KSTEEP * (p1 - t0 + half)) - fsigmoid(KSTEEP * (p1 - t0 - half));
            vy1 = fsigmoid(KSTEEP * (p1 - t1 + half)) - fsigmoid(KSTEEP * (p1 - t1 - half));
        }

        // ---- gather this lane's vy float4: vy[4*c14 .. 4*c14+3] ----
        float4 vyq;
        {
            int j = 4 * c14;
            float aA, aB;
            aA = __shfl_sync(0xffffffffu, vy0, j & 31);
            aB = __shfl_sync(0xffffffffu, vy1, j & 31);
            vyq.x = (j < 32) ? aA : aB;
            aA = __shfl_sync(0xffffffffu, vy0, (j + 1) & 31);
            aB = __shfl_sync(0xffffffffu, vy1, (j + 1) & 31);
            vyq.y = (j + 1 < 32) ? aA : aB;
            aA = __shfl_sync(0xffffffffu, vy0, (j + 2) & 31);
            aB = __shfl_sync(0xffffffffu, vy1, (j + 2) & 31);
            vyq.z = (j + 2 < 32) ? aA : aB;
            aA = __shfl_sync(0xffffffffu, vy0, (j + 3) & 31);
            aB = __shfl_sync(0xffffffffu, vy1, (j + 3) & 31);
            vyq.w = (j + 3 < 32) ? aA : aB;
        }

        // ---- raster: iter p stores rows 2p (lanes 0-13) and 2p+1 (14-27) ----
        float4* __restrict__ o4 = (float4*)(out + (size_t)r * (S * S));
        #pragma unroll
        for (int p = 0; p < S / 2; p++) {
            float srcv = (p < 16) ? vx0 : vx1;
            float vxE = __shfl_sync(0xffffffffu, srcv, (2 * p) & 31);
            float vxO = __shfl_sync(0xffffffffu, srcv, (2 * p + 1) & 31);
            float vxi = (lane < 14) ? vxE : vxO;
            if (lane < 28) {
                float4 rr;
                rr.x = vxi * vyq.x;
                rr.y = vxi * vyq.y;
                rr.z = vxi * vyq.z;
                rr.w = vxi * vyq.w;
                o4[p * 28 + lane] = rr;         // STG.128, 448B/iter contiguous
            }
        }
    }
}

// ---------------------------------------------------------------------------
// Launch. Inputs: x[B,D], W1[D,H], b1[H], W2[H,3], b2[3]. Output: [B,56,56] f32.
// ---------------------------------------------------------------------------
extern "C" void kernel_launch(void* const* d_in, const int* in_sizes, int n_in,
                              void* d_out, int out_size) {
    const float* x  = (const float*)d_in[0];
    const float* W1 = (const float*)d_in[1];
    const float* b1 = (const float*)d_in[2];
    const float* W2 = (const float*)d_in[3];
    const float* b2 = (const float*)d_in[4];
    float* out = (float*)d_out;

    const int H = in_sizes[2];           // 512
    const int D = in_sizes[1] / H;       // 1024
    const int B = in_sizes[0] / D;       // 16384

    {
        int threads = 256;
        int blocks = (D * 32 + threads - 1) / threads;   // warp per d-row
        weff_kernel<<<blocks, threads>>>(W1, b1, W2, b2, D, H);
    }
    {
        int threads = 256;
        int warps_needed = B;                            // 1 row/warp minimum work
        int max_blocks = NSM * BLK_PER_SM;               // single resident wave
        int blocks = (warps_needed * 32 + threads - 1) / threads;
        if (blocks > max_blocks) blocks = max_blocks;
        boxcar_kernel<<<blocks, threads>>>(x, out, B, D);
    }
}

// round 10
// speedup vs baseline: 1.1013x; 1.1013x over previous
#include <cuda_runtime.h>
#include <cuda_bf16.h>
#include <cstdint>

// out[b,i,j] = Vx(i; t0,t2) * Vy(j; t1,t2), with
//   t = x @ (W1@W2) + (b1@W2 + b2)   (the two linears collapse)
// Kernel A: Weff[1024,3] (split arrays) + beff[3], W2 staged in smem.
// Kernel B: block owns 8 CONSECUTIVE images.
//   Phase 1: warp w does GEMV for image w -> Vx/Vy into smem.
//   Phase 2: whole block streams its 100KB output region in flat address
//   order (4KB contiguous per 256-thread round) -> DRAM page locality.

#define MAX_D 1024
#define MAX_H 512
#define S 56
#define KSTEEP 10.0f
#define IMGS_PER_BLK 8

__device__ float g_w0[MAX_D];
__device__ float g_w1[MAX_D];
__device__ float g_w2[MAX_D];
__device__ float g_beff[3];

// ---------------------------------------------------------------------------
// Kernel A: Weff = W1 @ W2 (warp per d-row, W2 staged in smem),
//           beff = b1 @ W2 + b2 (one warp in block 0).
// ---------------------------------------------------------------------------
__global__ __launch_bounds__(256) void weff_kernel(const float* __restrict__ W1,
                                                   const float* __restrict__ b1,
                                                   const float* __restrict__ W2,
                                                   const float* __restrict__ b2,
                                                   int D, int H) {
    __shared__ float s_W2[MAX_H * 3];

    const int nW2 = H * 3;
    for (int idx = threadIdx.x; idx < nW2; idx += blockDim.x)
        s_W2[idx] = W2[idx];
    __syncthreads();

    const int lane = threadIdx.x & 31;
    const int warp = (blockIdx.x * blockDim.x + threadIdx.x) >> 5;

    if (warp < D) {
        const float4* __restrict__ row4 = (const float4*)(W1 + (size_t)warp * H);
        const int nch = H >> 2;
        float a0 = 0.f, a1 = 0.f, a2 = 0.f;
        #pragma unroll 4
        for (int c = lane; c < nch; c += 32) {
            float4 w = row4[c];
            int h = c << 2;
            a0 = fmaf(w.x, s_W2[(h+0)*3+0], fmaf(w.y, s_W2[(h+1)*3+0],
                 fmaf(w.z, s_W2[(h+2)*3+0], fmaf(w.w, s_W2[(h+3)*3+0], a0))));
            a1 = fmaf(w.x, s_W2[(h+0)*3+1], fmaf(w.y, s_W2[(h+1)*3+1],
                 fmaf(w.z, s_W2[(h+2)*3+1], fmaf(w.w, s_W2[(h+3)*3+1], a1))));
            a2 = fmaf(w.x, s_W2[(h+0)*3+2], fmaf(w.y, s_W2[(h+1)*3+2],
                 fmaf(w.z, s_W2[(h+2)*3+2], fmaf(w.w, s_W2[(h+3)*3+2], a2))));
        }
        #pragma unroll
        for (int o = 16; o > 0; o >>= 1) {
            a0 += __shfl_xor_sync(0xffffffffu, a0, o);
            a1 += __shfl_xor_sync(0xffffffffu, a1, o);
            a2 += __shfl_xor_sync(0xffffffffu, a2, o);
        }
        if (lane == 0) {
            g_w0[warp] = a0;
            g_w1[warp] = a1;
            g_w2[warp] = a2;
        }
    }

    if (blockIdx.x == 0 && threadIdx.x < 32) {
        float s0 = 0.f, s1 = 0.f, s2 = 0.f;
        for (int h = lane; h < H; h += 32) {
            float bv = b1[h];
            s0 = fmaf(bv, s_W2[h * 3 + 0], s0);
            s1 = fmaf(bv, s_W2[h * 3 + 1], s1);
            s2 = fmaf(bv, s_W2[h * 3 + 2], s2);
        }
        #pragma unroll
        for (int o = 16; o > 0; o >>= 1) {
            s0 += __shfl_xor_sync(0xffffffffu, s0, o);
            s1 += __shfl_xor_sync(0xffffffffu, s1, o);
            s2 += __shfl_xor_sync(0xffffffffu, s2, o);
        }
        if (lane == 0) {
            g_beff[0] = s0 + b2[0];
            g_beff[1] = s1 + b2[1];
            g_beff[2] = s2 + b2[2];
        }
    }
}

// ---------------------------------------------------------------------------
// Kernel B
// ---------------------------------------------------------------------------
__device__ __forceinline__ float fsigmoid(float z) {
    return 1.0f / (1.0f + __expf(-z));
}

__global__ __launch_bounds__(256, 6) void boxcar_kernel(
        const float* __restrict__ x, float* __restrict__ out, int B, int D) {
    __shared__ __align__(16) float s_w0[MAX_D];
    __shared__ __align__(16) float s_w1[MAX_D];
    __shared__ __align__(16) float s_w2[MAX_D];
    __shared__ __align__(16) float s_vx[IMGS_PER_BLK][64];
    __shared__ __align__(16) float s_vy[IMGS_PER_BLK][64];

    for (int e = threadIdx.x; e < D; e += blockDim.x) {
        s_w0[e] = g_w0[e];
        s_w1[e] = g_w1[e];
        s_w2[e] = g_w2[e];
    }
    __syncthreads();

    const int tid  = threadIdx.x;
    const int lane = tid & 31;
    const int wid  = tid >> 5;
    const int base = blockIdx.x * IMGS_PER_BLK;
    const int row  = base + wid;
    const int nch  = D >> 2;                    // 256 for D=1024

    // ---------------- Phase 1: GEMV + profiles into smem ----------------
    if (row < B) {
        const float4* __restrict__ x4 = (const float4*)(x + (size_t)row * D);
        float a0 = 0.f, a1 = 0.f, a2 = 0.f;
        #pragma unroll 4
        for (int c = lane; c < nch; c += 32) {
            float4 xv = x4[c];                  // LDG.128, coalesced
            int e = c << 2;
            float4 w0 = *(const float4*)&s_w0[e];
            float4 w1 = *(const float4*)&s_w1[e];
            float4 w2 = *(const float4*)&s_w2[e];
            a0 = fmaf(xv.x, w0.x, fmaf(xv.y, w0.y, fmaf(xv.z, w0.z, fmaf(xv.w, w0.w, a0))));
            a1 = fmaf(xv.x, w1.x, fmaf(xv.y, w1.y, fmaf(xv.z, w1.z, fmaf(xv.w, w1.w, a1))));
            a2 = fmaf(xv.x, w2.x, fmaf(xv.y, w2.y, fmaf(xv.z, w2.z, fmaf(xv.w, w2.w, a2))));
        }
        #pragma unroll
        for (int o = 16; o > 0; o >>= 1) {
            a0 += __shfl_xor_sync(0xffffffffu, a0, o);
            a1 += __shfl_xor_sync(0xffffffffu, a1, o);
            a2 += __shfl_xor_sync(0xffffffffu, a2, o);
        }
        const float t0 = a0 + g_beff[0];   // x center (rows i)
        const float t1 = a1 + g_beff[1];   // y center (cols j)
        const float t2 = a2 + g_beff[2];   // size

        const float half = 0.5f * t2;
        const float p0 = (float)lane;
        const float p1 = (float)(lane + 32);

        s_vx[wid][lane] = fsigmoid(KSTEEP * (p0 - t0 + half))
                        - fsigmoid(KSTEEP * (p0 - t0 - half));
        s_vy[wid][lane] = fsigmoid(KSTEEP * (p0 - t1 + half))
                        - fsigmoid(KSTEEP * (p0 - t1 - half));
        if (lane < S - 32) {
            s_vx[wid][lane + 32] = fsigmoid(KSTEEP * (p1 - t0 + half))
                                 - fsigmoid(KSTEEP * (p1 - t0 - half));
            s_vy[wid][lane + 32] = fsigmoid(KSTEEP * (p1 - t1 + half))
                                 - fsigmoid(KSTEEP * (p1 - t1 - half));
        }
    }
    __syncthreads();

    // ---------------- Phase 2: flat sequential store stream ----------------
    // Block region = IMGS_PER_BLK * 3136 floats = 6272 float4 (100KB contig).
    // Thread handles flat positions k = tid + 256*q within each image
    // (784 float4/image = 3 full rounds + 16). (i, j4) reused across images.
    int iq[4], jq[4];
    bool vq[4];
    #pragma unroll
    for (int q = 0; q < 4; q++) {
        int k = tid + 256 * q;
        vq[q] = (k < (S * S) / 4);              // 784
        int kk = vq[q] ? k : 0;
        iq[q] = kk / 14;                        // const-div -> mul.hi
        jq[q] = (kk - iq[q] * 14) << 2;
    }

    const int nimg = min(IMGS_PER_BLK, B - base);
    float4* __restrict__ o4 = (float4*)(out + (size_t)base * (S * S));

    #pragma unroll 2
    for (int img = 0; img < IMGS_PER_BLK; img++) {
        if (img >= nimg) break;
        float4* __restrict__ dst = o4 + img * ((S * S) / 4);
        const float* __restrict__ vx = s_vx[img];
        const float* __restrict__ vy = s_vy[img];
        #pragma unroll
        for (int q = 0; q < 4; q++) {
            if (vq[q]) {
                float vxi = vx[iq[q]];
                float4 v4 = *(const float4*)&vy[jq[q]];
                float4 rr;
                rr.x = vxi * v4.x;
                rr.y = vxi * v4.y;
                rr.z = vxi * v4.z;
                rr.w = vxi * v4.w;
                dst[tid + 256 * q] = rr;        // STG.128, 4KB/round contiguous
            }
        }
    }
}

// ---------------------------------------------------------------------------
// Launch. Inputs: x[B,D], W1[D,H], b1[H], W2[H,3], b2[3]. Output: [B,56,56] f32.
// ---------------------------------------------------------------------------
extern "C" void kernel_launch(void* const* d_in, const int* in_sizes, int n_in,
                              void* d_out, int out_size) {
    const float* x  = (const float*)d_in[0];
    const float* W1 = (const float*)d_in[1];
    const float* b1 = (const float*)d_in[2];
    const float* W2 = (const float*)d_in[3];
    const float* b2 = (const float*)d_in[4];
    float* out = (float*)d_out;

    const int H = in_sizes[2];           // 512
    const int D = in_sizes[1] / H;       // 1024
    const int B = in_sizes[0] / D;       // 16384

    {
        int threads = 256;
        int blocks = (D * 32 + threads - 1) / threads;   // warp per d-row
        weff_kernel<<<blocks, threads>>>(W1, b1, W2, b2, D, H);
    }
    {
        int threads = 256;
        int blocks = (B + IMGS_PER_BLK - 1) / IMGS_PER_BLK;   // 2048
        boxcar_kernel<<<blocks, threads>>>(x, out, B, D);
    }
}

// round 11
// speedup vs baseline: 1.2314x; 1.1182x over previous
#include <cuda_runtime.h>
#include <cuda_bf16.h>
#include <cstdint>

// out[b,i,j] = Vx(i; t0,t2) * Vy(j; t1,t2), with
//   t = x @ (W1@W2) + (b1@W2 + b2)   (the two linears collapse)
// Kernel A: Weff[1024,3] (split arrays) + beff[3], W2 staged in smem.
// Kernel B: proven R7 structure (warp per row, float4 GEMV, STG.64 raster),
//   plus cache-policy hints: __stcs on output (evict-first dirty lines ->
//   prompt, near-in-order L2->DRAM eviction) and __ldcs on streaming x reads
//   (don't pollute L2 write buffering).

#define MAX_D 1024
#define MAX_H 512
#define S 56
#define KSTEEP 10.0f

__device__ float g_w0[MAX_D];
__device__ float g_w1[MAX_D];
__device__ float g_w2[MAX_D];
__device__ float g_beff[3];

// ---------------------------------------------------------------------------
// Kernel A: Weff = W1 @ W2 (warp per d-row, W2 staged in smem),
//           beff = b1 @ W2 + b2 (one warp in block 0).
// ---------------------------------------------------------------------------
__global__ __launch_bounds__(256) void weff_kernel(const float* __restrict__ W1,
                                                   const float* __restrict__ b1,
                                                   const float* __restrict__ W2,
                                                   const float* __restrict__ b2,
                                                   int D, int H) {
    __shared__ float s_W2[MAX_H * 3];

    const int nW2 = H * 3;
    for (int idx = threadIdx.x; idx < nW2; idx += blockDim.x)
        s_W2[idx] = W2[idx];
    __syncthreads();

    const int lane = threadIdx.x & 31;
    const int warp = (blockIdx.x * blockDim.x + threadIdx.x) >> 5;

    if (warp < D) {
        const float4* __restrict__ row4 = (const float4*)(W1 + (size_t)warp * H);
        const int nch = H >> 2;                 // 128 for H=512
        float a0 = 0.f, a1 = 0.f, a2 = 0.f;
        #pragma unroll 4
        for (int c = lane; c < nch; c += 32) {
            float4 w = __ldcs(&row4[c]);        // streaming LDG.128
            int h = c << 2;
            a0 = fmaf(w.x, s_W2[(h+0)*3+0], fmaf(w.y, s_W2[(h+1)*3+0],
                 fmaf(w.z, s_W2[(h+2)*3+0], fmaf(w.w, s_W2[(h+3)*3+0], a0))));
            a1 = fmaf(w.x, s_W2[(h+0)*3+1], fmaf(w.y, s_W2[(h+1)*3+1],
                 fmaf(w.z, s_W2[(h+2)*3+1], fmaf(w.w, s_W2[(h+3)*3+1], a1))));
            a2 = fmaf(w.x, s_W2[(h+0)*3+2], fmaf(w.y, s_W2[(h+1)*3+2],
                 fmaf(w.z, s_W2[(h+2)*3+2], fmaf(w.w, s_W2[(h+3)*3+2], a2))));
        }
        #pragma unroll
        for (int o = 16; o > 0; o >>= 1) {
            a0 += __shfl_xor_sync(0xffffffffu, a0, o);
            a1 += __shfl_xor_sync(0xffffffffu, a1, o);
            a2 += __shfl_xor_sync(0xffffffffu, a2, o);
        }
        if (lane == 0) {
            g_w0[warp] = a0;
            g_w1[warp] = a1;
            g_w2[warp] = a2;
        }
    }

    if (blockIdx.x == 0 && threadIdx.x < 32) {
        float s0 = 0.f, s1 = 0.f, s2 = 0.f;
        for (int h = lane; h < H; h += 32) {
            float bv = b1[h];
            s0 = fmaf(bv, s_W2[h * 3 + 0], s0);
            s1 = fmaf(bv, s_W2[h * 3 + 1], s1);
            s2 = fmaf(bv, s_W2[h * 3 + 2], s2);
        }
        #pragma unroll
        for (int o = 16; o > 0; o >>= 1) {
            s0 += __shfl_xor_sync(0xffffffffu, s0, o);
            s1 += __shfl_xor_sync(0xffffffffu, s1, o);
            s2 += __shfl_xor_sync(0xffffffffu, s2, o);
        }
        if (lane == 0) {
            g_beff[0] = s0 + b2[0];
            g_beff[1] = s1 + b2[1];
            g_beff[2] = s2 + b2[2];
        }
    }
}

// ---------------------------------------------------------------------------
// Kernel B: one warp per batch row (proven R7 structure + cache hints).
// ---------------------------------------------------------------------------
__device__ __forceinline__ float fsigmoid(float z) {
    return 1.0f / (1.0f + __expf(-z));
}

__global__ __launch_bounds__(256) void boxcar_kernel(const float* __restrict__ x,
                                                     float* __restrict__ out,
                                                     int B, int D) {
    __shared__ __align__(16) float s_w0[MAX_D];
    __shared__ __align__(16) float s_w1[MAX_D];
    __shared__ __align__(16) float s_w2[MAX_D];

    for (int e = threadIdx.x; e < D; e += blockDim.x) {
        s_w0[e] = g_w0[e];
        s_w1[e] = g_w1[e];
        s_w2[e] = g_w2[e];
    }
    __syncthreads();

    const int lane = threadIdx.x & 31;
    const int wid  = threadIdx.x >> 5;
    const int row  = blockIdx.x * (blockDim.x >> 5) + wid;
    if (row >= B) return;

    // ---- skinny GEMV, float4-vectorized: 8 LDG.128 + 24 LDS.128 per lane ----
    const float4* __restrict__ x4 = (const float4*)(x + (size_t)row * D);
    const int nch = D >> 2;                     // 256 for D=1024
    float a0 = 0.f, a1 = 0.f, a2 = 0.f;
    #pragma unroll 4
    for (int c = lane; c < nch; c += 32) {
        float4 xv = __ldcs(&x4[c]);             // streaming LDG.128
        int e = c << 2;
        float4 w0 = *(const float4*)&s_w0[e];
        float4 w1 = *(const float4*)&s_w1[e];
        float4 w2 = *(const float4*)&s_w2[e];
        a0 = fmaf(xv.x, w0.x, fmaf(xv.y, w0.y, fmaf(xv.z, w0.z, fmaf(xv.w, w0.w, a0))));
        a1 = fmaf(xv.x, w1.x, fmaf(xv.y, w1.y, fmaf(xv.z, w1.z, fmaf(xv.w, w1.w, a1))));
        a2 = fmaf(xv.x, w2.x, fmaf(xv.y, w2.y, fmaf(xv.z, w2.z, fmaf(xv.w, w2.w, a2))));
    }
    #pragma unroll
    for (int o = 16; o > 0; o >>= 1) {
        a0 += __shfl_xor_sync(0xffffffffu, a0, o);
        a1 += __shfl_xor_sync(0xffffffffu, a1, o);
        a2 += __shfl_xor_sync(0xffffffffu, a2, o);
    }
    const float t0 = a0 + g_beff[0];   // x center (maps to i)
    const float t1 = a1 + g_beff[1];   // y center (maps to j)
    const float t2 = a2 + g_beff[2];   // size

    // ---- boxcar profiles: lane covers coords lane and lane+32 ----
    const float half = 0.5f * t2;
    const float c0 = (float)lane;
    const float c1 = (float)(lane + 32);

    float vx0 = fsigmoid(KSTEEP * (c0 - t0 + half)) - fsigmoid(KSTEEP * (c0 - t0 - half));
    float vy0 = fsigmoid(KSTEEP * (c0 - t1 + half)) - fsigmoid(KSTEEP * (c0 - t1 - half));
    float vx1 = 0.f, vy1 = 0.f;
    if (lane < S - 32) {
        vx1 = fsigmoid(KSTEEP * (c1 - t0 + half)) - fsigmoid(KSTEEP * (c1 - t0 - half));
        vy1 = fsigmoid(KSTEEP * (c1 - t1 + half)) - fsigmoid(KSTEEP * (c1 - t1 - half));
    }

    // ---- gather vy pair for this lane: vy[2*lane], vy[2*lane+1] (lanes 0-27) ----
    const int e_idx = 2 * lane;
    const int o_idx = 2 * lane + 1;
    float eA = __shfl_sync(0xffffffffu, vy0, e_idx & 31);
    float eB = __shfl_sync(0xffffffffu, vy1, e_idx & 31);
    float oA = __shfl_sync(0xffffffffu, vy0, o_idx & 31);
    float oB = __shfl_sync(0xffffffffu, vy1, o_idx & 31);
    const float vyA = (e_idx < 32) ? eA : eB;
    const float vyB = (o_idx < 32) ? oA : oB;

    // ---- rasterize: one STG.64.CS per output row (lanes 0-27) ----
    float2* __restrict__ o2 = (float2*)(out + (size_t)row * (S * S));
    #pragma unroll
    for (int i = 0; i < S; i++) {
        float src = (i < 32) ? vx0 : vx1;
        float vxi = __shfl_sync(0xffffffffu, src, i & 31);
        if (lane < S / 2) {
            float2 r;
            r.x = vxi * vyA;
            r.y = vxi * vyB;
            __stcs(&o2[lane], r);               // evict-first: prompt eviction
        }
        o2 += S / 2;
    }
}

// ---------------------------------------------------------------------------
// Launch. Inputs: x[B,D], W1[D,H], b1[H], W2[H,3], b2[3]. Output: [B,56,56] f32.
// ---------------------------------------------------------------------------
extern "C" void kernel_launch(void* const* d_in, const int* in_sizes, int n_in,
                              void* d_out, int out_size) {
    const float* x  = (const float*)d_in[0];
    const float* W1 = (const float*)d_in[1];
    const float* b1 = (const float*)d_in[2];
    const float* W2 = (const float*)d_in[3];
    const float* b2 = (const float*)d_in[4];
    float* out = (float*)d_out;

    const int H = in_sizes[2];           // 512
    const int D = in_sizes[1] / H;       // 1024
    const int B = in_sizes[0] / D;       // 16384

    {
        int threads = 256;
        int blocks = (D * 32 + threads - 1) / threads;   // warp per d-row
        weff_kernel<<<blocks, threads>>>(W1, b1, W2, b2, D, H);
    }
    {
        int threads = 256;
        int rows_per_block = threads / 32;
        int blocks = (B + rows_per_block - 1) / rows_per_block;
        boxcar_kernel<<<blocks, threads>>>(x, out, B, D);
    }
}